// round 14
// baseline (speedup 1.0000x reference)
#include <cuda_runtime.h>
#include <cuda_fp16.h>
#include <cstdint>
#include <cstddef>

// ---------------------------------------------------------------------------
// Attention_87428354277788 — R14: R11 math (pure single-fp16 HMMA) with
// L1-traffic-optimized GEMM: warp tile 64x64 (0.5 ldsm/MMA), 4-warp CTAs,
// 3 CTA/SM. Convert kernel restored (fp32-A fusion reverted — it added L1
// traffic to an L1-bound kernel).
// ---------------------------------------------------------------------------

typedef unsigned long long u64;
typedef __half fp16;

__device__ float g_bias[786432];       // [12, 256, 256]
__device__ fp16  g_ah[25165824];       // x hi, then attn-out hi [32768,768]
__device__ fp16  g_qh[25165824];       // Q hi [32768,768]
__device__ fp16  g_kh[25165824];       // K hi
__device__ fp16  g_vh[25165824];       // V hi
__device__ fp16  g_bqh[1769472];       // WqkvT hi [2304,768]
__device__ fp16  g_boh[589824];        // WoutT hi [768,768]

// ---------------------------------------------------------------------------
__device__ __forceinline__ uint32_t smem_u32(const void* p) {
    uint32_t a;
    asm("{ .reg .u64 t; cvta.to.shared.u64 t, %1; cvt.u32.u64 %0, t; }"
        : "=r"(a) : "l"(p));
    return a;
}
__device__ __forceinline__ void cp16(uint32_t s, const void* g) {
    asm volatile("cp.async.cg.shared.global [%0], [%1], 16;" :: "r"(s), "l"(g));
}
#define CP_COMMIT() asm volatile("cp.async.commit_group;" ::: "memory")
#define CP_WAIT0()  asm volatile("cp.async.wait_group 0;" ::: "memory")
#define CP_WAIT1()  asm volatile("cp.async.wait_group 1;" ::: "memory")

__device__ __forceinline__ void ldsm4(uint32_t* r, uint32_t addr) {
    asm volatile("ldmatrix.sync.aligned.m8n8.x4.shared.b16 {%0,%1,%2,%3}, [%4];"
        : "=r"(r[0]), "=r"(r[1]), "=r"(r[2]), "=r"(r[3]) : "r"(addr));
}
__device__ __forceinline__ void mma_fp16(float* c, const uint32_t* a,
                                         const uint32_t* b) {
    asm volatile(
        "mma.sync.aligned.m16n8k16.row.col.f32.f16.f16.f32 "
        "{%0,%1,%2,%3}, {%4,%5,%6,%7}, {%8,%9}, {%0,%1,%2,%3};"
        : "+f"(c[0]), "+f"(c[1]), "+f"(c[2]), "+f"(c[3])
        : "r"(a[0]), "r"(a[1]), "r"(a[2]), "r"(a[3]), "r"(b[0]), "r"(b[1]));
}
__device__ __forceinline__ uint32_t h2pack(float a, float b) {
    __half2 h = __floats2half2_rn(a, b);
    return *(uint32_t*)&h;
}

// ---------------------------------------------------------------------------
__global__ void convert_kernel(const float* __restrict__ in,
                               fp16* __restrict__ hi, int n4)
{
    int i = blockIdx.x * 256 + threadIdx.x;
    if (i >= n4) return;
    float4 v = ((const float4*)in)[i];
    ((ushort4*)hi)[i] = make_ushort4(
        __half_as_ushort(__float2half_rn(v.x)),
        __half_as_ushort(__float2half_rn(v.y)),
        __half_as_ushort(__float2half_rn(v.z)),
        __half_as_ushort(__float2half_rn(v.w)));
}

__global__ void split_transpose_kernel(const float* __restrict__ in,
                                       fp16* __restrict__ outh, int R, int C)
{
    __shared__ float t[32][33];
    int c0 = blockIdx.x * 32, r0 = blockIdx.y * 32;
#pragma unroll
    for (int i = threadIdx.y; i < 32; i += 8)
        t[i][threadIdx.x] = in[(size_t)(r0 + i) * C + c0 + threadIdx.x];
    __syncthreads();
#pragma unroll
    for (int i = threadIdx.y; i < 32; i += 8)
        outh[(size_t)(c0 + i) * R + r0 + threadIdx.x] =
            __float2half_rn(t[threadIdx.x][i]);
}

__global__ void bias_gather_kernel(const int* __restrict__ ids,
                                   const float* __restrict__ table,
                                   float* __restrict__ biasmat)
{
    int pos = blockIdx.x * 256 + threadIdx.x;
    int id = ids[pos];
#pragma unroll
    for (int h = 0; h < 12; h++)
        biasmat[h * 65536 + pos] = table[id * 12 + h];
}

// ---------------------------------------------------------------------------
// Single-fp16 GEMM: C = Ah@Bh^T + bias.
// CTA 128x128, 4 warps (2M x 2N, warp tile 64x64), 128 threads, BK=32,
// 3-stage cp.async, 3 CTA/SM.
// mode 0: fp32 C.  mode 1: QKV epilogue -> Q/K/V hi fp16 [token][768].
// ---------------------------------------------------------------------------
#define RSB   80
#define PARTB 10240
#define STG   20480
#define GSM   (3 * STG)

__global__ __launch_bounds__(128, 3) void hgemm_kernel(
    const fp16* __restrict__ Ah, const fp16* __restrict__ Bh,
    const float* __restrict__ bias, float* __restrict__ C,
    fp16* __restrict__ oqh, fp16* __restrict__ okh, fp16* __restrict__ ovh,
    int M, int N, int K, int mode)
{
    extern __shared__ char smraw[];
    const uint32_t sbase = smem_u32(smraw);
    const int tid = threadIdx.x;
    const int lane = tid & 31;
    const int wid = tid >> 5;
    const int warp_m = wid & 1;      // 2 warps over M (64 rows)
    const int warp_n = wid >> 1;     // 2 warps over N (64 cols)
    const int m0 = blockIdx.y * 128;
    const int n0 = blockIdx.x * 128;

    const fp16* Ah_g = Ah + (size_t)m0 * K;
    const fp16* Bh_g = Bh + (size_t)n0 * K;

    const uint32_t a_lane = (uint32_t)((lane & 15) * RSB + (lane >> 4) * 16
                          + warp_m * 64 * RSB);
    const uint32_t b_lane = (uint32_t)(((lane & 7) + (lane >> 4) * 8) * RSB
                          + ((lane >> 3) & 1) * 16 + warp_n * 64 * RSB);

    float acc[4][8][4];
#pragma unroll
    for (int i = 0; i < 4; i++)
#pragma unroll
        for (int j = 0; j < 8; j++)
#pragma unroll
            for (int q = 0; q < 4; q++) acc[i][j][q] = 0.f;

    const int nch = K >> 5;          // 24

#define LOAD_STAGE(ch) do {                                                    \
        const int k0_ = (ch) << 5;                                             \
        const uint32_t sst = sbase + (uint32_t)((ch) % 3) * STG;               \
        _Pragma("unroll")                                                      \
        for (int s = 0; s < 4; s++) {                                          \
            cp16(sst + tid * RSB + s * 16,                                     \
                 Ah_g + (size_t)tid * K + k0_ + s * 8);                        \
            cp16(sst + PARTB + tid * RSB + s * 16,                             \
                 Bh_g + (size_t)tid * K + k0_ + s * 8);                        \
        }                                                                      \
        CP_COMMIT();                                                           \
    } while (0)

    LOAD_STAGE(0);
    LOAD_STAGE(1);

    for (int ch = 0; ch < nch; ch++) {
        if (ch + 1 < nch) CP_WAIT1(); else CP_WAIT0();
        __syncthreads();
        if (ch + 2 < nch) LOAD_STAGE(ch + 2);

        const uint32_t sbuf = sbase + (uint32_t)(ch % 3) * STG;
        const uint32_t sAh = sbuf + a_lane;
        const uint32_t sBh = sbuf + PARTB + b_lane;

#pragma unroll
        for (int ko = 0; ko < 2; ko++) {
            const uint32_t kb = ko * 32;
            uint32_t bh[4][4];
#pragma unroll
            for (int nt16 = 0; nt16 < 4; nt16++)
                ldsm4(bh[nt16], sBh + nt16 * (16 * RSB) + kb);
#pragma unroll
            for (int mt = 0; mt < 4; mt++) {
                uint32_t ah[4];
                ldsm4(ah, sAh + mt * (16 * RSB) + kb);
#pragma unroll
                for (int nt16 = 0; nt16 < 4; nt16++) {
                    mma_fp16(acc[mt][2 * nt16],     ah, &bh[nt16][0]);
                    mma_fp16(acc[mt][2 * nt16 + 1], ah, &bh[nt16][2]);
                }
            }
        }
    }
#undef LOAD_STAGE

    const int quad = lane >> 2, tq = lane & 3;
    const int region = n0 / 768;
#pragma unroll
    for (int mt = 0; mt < 4; mt++) {
        const int r = m0 + warp_m * 64 + mt * 16 + quad;
#pragma unroll
        for (int nt = 0; nt < 8; nt++) {
            const int c = n0 + warp_n * 64 + nt * 8 + tq * 2;
            const float b0 = bias[c], b1 = bias[c + 1];
            float v0 = acc[mt][nt][0] + b0, v1 = acc[mt][nt][1] + b1;
            float v2 = acc[mt][nt][2] + b0, v3 = acc[mt][nt][3] + b1;
            if (mode == 0) {
                float* cp = C + (size_t)r * N + c;
                *(float2*)cp = make_float2(v0, v1);
                *(float2*)(cp + 8 * (size_t)N) = make_float2(v2, v3);
            } else {
                const int cc = c - region * 768;
                size_t o0 = (size_t)r * 768 + cc;
                size_t o1 = o0 + 8 * 768;
                fp16* dst = (region == 0) ? oqh : (region == 1) ? okh : ovh;
                *(uint32_t*)(dst + o0) = h2pack(v0, v1);
                *(uint32_t*)(dst + o1) = h2pack(v2, v3);
            }
        }
    }
}

// ---------------------------------------------------------------------------
// HMMA flash attention (fp32 acc, pure fp16 operands) — unchanged from R11.
// ---------------------------------------------------------------------------
#define ARS 144
#define A_QH 0
#define A_KH 9216
#define A_VT 18432
#define A_SM 27648

__global__ __launch_bounds__(128) void attn_mma_kernel(
    const fp16* __restrict__ qh, const fp16* __restrict__ kh,
    const fp16* __restrict__ vh,
    const float* __restrict__ biasmat, fp16* __restrict__ out_h)
{
    __shared__ char smem[A_SM];
    const uint32_t sb = smem_u32(smem);
    const int qt = blockIdx.x, h = blockIdx.y, b = blockIdx.z;
    const int tid = threadIdx.x, lane = tid & 31, wid = tid >> 5;
    const int q0 = qt * 64;
    const size_t tok0 = (size_t)b * 256;

    {
        const fp16* qg0 = qh + (tok0 + q0) * 768 + h * 64;
        int row = tid >> 1, sg0 = (tid & 1) * 4;
#pragma unroll
        for (int s = 0; s < 4; s++)
            cp16(sb + A_QH + row * ARS + (sg0 + s) * 16,
                 qg0 + row * 768 + (sg0 + s) * 8);
        CP_COMMIT();
    }

    const uint32_t a_lane = (uint32_t)((lane & 15) * ARS + (lane >> 4) * 16
                          + wid * 16 * ARS);
    const uint32_t b_lane = (uint32_t)(((lane & 7) + (lane >> 4) * 8) * ARS
                          + ((lane >> 3) & 1) * 16);

    float o[8][4];
#pragma unroll
    for (int t = 0; t < 8; t++)
#pragma unroll
        for (int q = 0; q < 4; q++) o[t][q] = 0.f;
    float m0 = -1e30f, m1 = -1e30f, l0 = 0.f, l1 = 0.f;

    const float* bb0 = biasmat + (size_t)h * 65536
                     + (size_t)(q0 + wid * 16 + (lane >> 2)) * 256 + 2 * (lane & 3);

    for (int kt = 0; kt < 4; kt++) {
        __syncthreads();
        {
            const fp16* kg = kh + (tok0 + kt * 64) * 768 + h * 64;
            int row = tid >> 1, sg0 = (tid & 1) * 4;
#pragma unroll
            for (int s = 0; s < 4; s++)
                cp16(sb + A_KH + row * ARS + (sg0 + s) * 16,
                     kg + row * 768 + (sg0 + s) * 8);
            CP_COMMIT();
        }
        {
            const fp16* vg = vh + (tok0 + kt * 64) * 768 + h * 64;
            int key = tid >> 1, dh0 = (tid & 1) * 32;
#pragma unroll
            for (int g = 0; g < 4; g++) {
                float4 vv = *(const float4*)(vg + (size_t)key * 768 + dh0 + g * 8);
                const unsigned short* u = (const unsigned short*)&vv;
#pragma unroll
                for (int e = 0; e < 8; e++)
                    *(unsigned short*)(smem + A_VT + (dh0 + g * 8 + e) * ARS + key * 2) = u[e];
            }
        }
        CP_WAIT0();
        __syncthreads();

        float c[8][4];
#pragma unroll
        for (int t = 0; t < 8; t++)
#pragma unroll
            for (int q = 0; q < 4; q++) c[t][q] = 0.f;

#pragma unroll
        for (int j = 0; j < 4; j++) {
            uint32_t aqh[4];
            ldsm4(aqh, sb + A_QH + a_lane + j * 32);
#pragma unroll
            for (int g = 0; g < 4; g++) {
                uint32_t bk[4];
                ldsm4(bk, sb + A_KH + b_lane + g * (16 * ARS) + j * 32);
                mma_fp16(c[2 * g],     aqh, &bk[0]);
                mma_fp16(c[2 * g + 1], aqh, &bk[2]);
            }
        }

        const float* bk0 = bb0 + kt * 64;
        float tm0 = -1e30f, tm1 = -1e30f;
#pragma unroll
        for (int t = 0; t < 8; t++) {
            float2 bv0 = *(const float2*)(bk0 + t * 8);
            float2 bv1 = *(const float2*)(bk0 + 8 * 256 + t * 8);
            c[t][0] = fmaf(c[t][0], 0.125f, bv0.x);
            c[t][1] = fmaf(c[t][1], 0.125f, bv0.y);
            c[t][2] = fmaf(c[t][2], 0.125f, bv1.x);
            c[t][3] = fmaf(c[t][3], 0.125f, bv1.y);
            tm0 = fmaxf(tm0, fmaxf(c[t][0], c[t][1]));
            tm1 = fmaxf(tm1, fmaxf(c[t][2], c[t][3]));
        }
        tm0 = fmaxf(tm0, __shfl_xor_sync(0xffffffffu, tm0, 1));
        tm0 = fmaxf(tm0, __shfl_xor_sync(0xffffffffu, tm0, 2));
        tm1 = fmaxf(tm1, __shfl_xor_sync(0xffffffffu, tm1, 1));
        tm1 = fmaxf(tm1, __shfl_xor_sync(0xffffffffu, tm1, 2));
        float mn0 = fmaxf(m0, tm0), mn1 = fmaxf(m1, tm1);
        float corr0 = __expf(m0 - mn0), corr1 = __expf(m1 - mn1);
        m0 = mn0; m1 = mn1;
        float ps0 = 0.f, ps1 = 0.f;
#pragma unroll
        for (int t = 0; t < 8; t++) {
            c[t][0] = __expf(c[t][0] - mn0);
            c[t][1] = __expf(c[t][1] - mn0);
            c[t][2] = __expf(c[t][2] - mn1);
            c[t][3] = __expf(c[t][3] - mn1);
            ps0 += c[t][0] + c[t][1];
            ps1 += c[t][2] + c[t][3];
        }
        ps0 += __shfl_xor_sync(0xffffffffu, ps0, 1);
        ps0 += __shfl_xor_sync(0xffffffffu, ps0, 2);
        ps1 += __shfl_xor_sync(0xffffffffu, ps1, 1);
        ps1 += __shfl_xor_sync(0xffffffffu, ps1, 2);
        l0 = l0 * corr0 + ps0;
        l1 = l1 * corr1 + ps1;
#pragma unroll
        for (int t = 0; t < 8; t++) {
            o[t][0] *= corr0; o[t][1] *= corr0;
            o[t][2] *= corr1; o[t][3] *= corr1;
        }

#pragma unroll
        for (int j = 0; j < 4; j++) {
            uint32_t ph[4];
#pragma unroll
            for (int half16 = 0; half16 < 2; half16++) {
                const float* cc = c[2 * j + half16];
                ph[2 * half16]     = h2pack(cc[0], cc[1]);
                ph[2 * half16 + 1] = h2pack(cc[2], cc[3]);
            }
#pragma unroll
            for (int g = 0; g < 4; g++) {
                uint32_t bv[4];
                ldsm4(bv, sb + A_VT + b_lane + g * (16 * ARS) + j * 32);
                mma_fp16(o[2 * g],     ph, &bv[0]);
                mma_fp16(o[2 * g + 1], ph, &bv[2]);
            }
        }
    }

    float inv0 = 1.0f / l0, inv1 = 1.0f / l1;
    const size_t t0 = tok0 + q0 + wid * 16 + (lane >> 2);
    const int colb = h * 64 + 2 * (lane & 3);
#pragma unroll
    for (int t = 0; t < 8; t++) {
        size_t o0 = t0 * 768 + colb + t * 8;
        size_t o1 = o0 + 8 * 768;
        *(uint32_t*)(out_h + o0) = h2pack(o[t][0] * inv0, o[t][1] * inv0);
        *(uint32_t*)(out_h + o1) = h2pack(o[t][2] * inv1, o[t][3] * inv1);
    }
}

// ---------------------------------------------------------------------------
extern "C" void kernel_launch(void* const* d_in, const int* in_sizes, int n_in,
                              void* d_out, int out_size)
{
    const float* x     = (const float*)d_in[0];
    const float* Wqkv  = (const float*)d_in[1];
    const float* bqkv  = (const float*)d_in[2];
    const float* Wout  = (const float*)d_in[3];
    const float* bout  = (const float*)d_in[4];
    const float* table = (const float*)d_in[5];
    const int*   ids   = (const int*)d_in[6];
    float* out = (float*)d_out;

    float* bias;
    fp16 *ah, *qh, *khp, *vhp, *bqh, *boh;
    cudaGetSymbolAddress((void**)&bias, g_bias);
    cudaGetSymbolAddress((void**)&ah,   g_ah);
    cudaGetSymbolAddress((void**)&qh,   g_qh);
    cudaGetSymbolAddress((void**)&khp,  g_kh);
    cudaGetSymbolAddress((void**)&vhp,  g_vh);
    cudaGetSymbolAddress((void**)&bqh,  g_bqh);
    cudaGetSymbolAddress((void**)&boh,  g_boh);

    cudaFuncSetAttribute(hgemm_kernel,
                         cudaFuncAttributeMaxDynamicSharedMemorySize, GSM);

    // prep
    split_transpose_kernel<<<dim3(2304 / 32, 768 / 32), dim3(32, 8)>>>(
        Wqkv, bqh, 768, 2304);
    split_transpose_kernel<<<dim3(768 / 32, 768 / 32), dim3(32, 8)>>>(
        Wout, boh, 768, 768);
    bias_gather_kernel<<<256, 256>>>(ids, table, bias);
    convert_kernel<<<25165824 / 4 / 256, 256>>>(x, ah, 25165824 / 4);

    // QKV projection -> fp16 Q/K/V (hi)
    hgemm_kernel<<<dim3(2304 / 128, 32768 / 128), 128, GSM>>>(
        ah, bqh, bqkv, nullptr, qh, khp, vhp, 32768, 2304, 768, 1);

    // pure-fp16 HMMA attention -> fp16 hi into ah
    attn_mma_kernel<<<dim3(4, 12, 128), 128>>>(qh, khp, vhp, bias, ah);

    // output projection -> fp32 out
    hgemm_kernel<<<dim3(768 / 128, 32768 / 128), 128, GSM>>>(
        ah, boh, bout, out, nullptr, nullptr, nullptr, 32768, 768, 768, 0);
}

// round 15
// speedup vs baseline: 1.0031x; 1.0031x over previous
#include <cuda_runtime.h>
#include <cuda_fp16.h>
#include <cstdint>
#include <cstddef>

// ---------------------------------------------------------------------------
// Attention_87428354277788 — R15: R14 geometry (warp tile 64x64, 4-warp CTA,
// 0.5x ldsm traffic) with the register-spill fixed: launch_bounds(128, 2)
// (cap 255, no spill) instead of (128, 3) (cap 170, spilled acc).
// Math identical to R11 (pure single-fp16 HMMA; rel_err 6.76e-4).
// ---------------------------------------------------------------------------

typedef unsigned long long u64;
typedef __half fp16;

__device__ float g_bias[786432];       // [12, 256, 256]
__device__ fp16  g_ah[25165824];       // x hi, then attn-out hi [32768,768]
__device__ fp16  g_qh[25165824];       // Q hi [32768,768]
__device__ fp16  g_kh[25165824];       // K hi
__device__ fp16  g_vh[25165824];       // V hi
__device__ fp16  g_bqh[1769472];       // WqkvT hi [2304,768]
__device__ fp16  g_boh[589824];        // WoutT hi [768,768]

// ---------------------------------------------------------------------------
__device__ __forceinline__ uint32_t smem_u32(const void* p) {
    uint32_t a;
    asm("{ .reg .u64 t; cvta.to.shared.u64 t, %1; cvt.u32.u64 %0, t; }"
        : "=r"(a) : "l"(p));
    return a;
}
__device__ __forceinline__ void cp16(uint32_t s, const void* g) {
    asm volatile("cp.async.cg.shared.global [%0], [%1], 16;" :: "r"(s), "l"(g));
}
#define CP_COMMIT() asm volatile("cp.async.commit_group;" ::: "memory")
#define CP_WAIT0()  asm volatile("cp.async.wait_group 0;" ::: "memory")
#define CP_WAIT1()  asm volatile("cp.async.wait_group 1;" ::: "memory")

__device__ __forceinline__ void ldsm4(uint32_t* r, uint32_t addr) {
    asm volatile("ldmatrix.sync.aligned.m8n8.x4.shared.b16 {%0,%1,%2,%3}, [%4];"
        : "=r"(r[0]), "=r"(r[1]), "=r"(r[2]), "=r"(r[3]) : "r"(addr));
}
__device__ __forceinline__ void mma_fp16(float* c, const uint32_t* a,
                                         const uint32_t* b) {
    asm volatile(
        "mma.sync.aligned.m16n8k16.row.col.f32.f16.f16.f32 "
        "{%0,%1,%2,%3}, {%4,%5,%6,%7}, {%8,%9}, {%0,%1,%2,%3};"
        : "+f"(c[0]), "+f"(c[1]), "+f"(c[2]), "+f"(c[3])
        : "r"(a[0]), "r"(a[1]), "r"(a[2]), "r"(a[3]), "r"(b[0]), "r"(b[1]));
}
__device__ __forceinline__ uint32_t h2pack(float a, float b) {
    __half2 h = __floats2half2_rn(a, b);
    return *(uint32_t*)&h;
}

// ---------------------------------------------------------------------------
__global__ void convert_kernel(const float* __restrict__ in,
                               fp16* __restrict__ hi, int n4)
{
    int i = blockIdx.x * 256 + threadIdx.x;
    if (i >= n4) return;
    float4 v = ((const float4*)in)[i];
    ((ushort4*)hi)[i] = make_ushort4(
        __half_as_ushort(__float2half_rn(v.x)),
        __half_as_ushort(__float2half_rn(v.y)),
        __half_as_ushort(__float2half_rn(v.z)),
        __half_as_ushort(__float2half_rn(v.w)));
}

__global__ void split_transpose_kernel(const float* __restrict__ in,
                                       fp16* __restrict__ outh, int R, int C)
{
    __shared__ float t[32][33];
    int c0 = blockIdx.x * 32, r0 = blockIdx.y * 32;
#pragma unroll
    for (int i = threadIdx.y; i < 32; i += 8)
        t[i][threadIdx.x] = in[(size_t)(r0 + i) * C + c0 + threadIdx.x];
    __syncthreads();
#pragma unroll
    for (int i = threadIdx.y; i < 32; i += 8)
        outh[(size_t)(c0 + i) * R + r0 + threadIdx.x] =
            __float2half_rn(t[threadIdx.x][i]);
}

__global__ void bias_gather_kernel(const int* __restrict__ ids,
                                   const float* __restrict__ table,
                                   float* __restrict__ biasmat)
{
    int pos = blockIdx.x * 256 + threadIdx.x;
    int id = ids[pos];
#pragma unroll
    for (int h = 0; h < 12; h++)
        biasmat[h * 65536 + pos] = table[id * 12 + h];
}

// ---------------------------------------------------------------------------
// Single-fp16 GEMM: C = Ah@Bh^T + bias.
// CTA 128x128, 4 warps (2M x 2N, warp tile 64x64), 128 threads, BK=32,
// 3-stage cp.async, 2 CTA/SM (reg cap 255 -> no spill).
// mode 0: fp32 C.  mode 1: QKV epilogue -> Q/K/V hi fp16 [token][768].
// ---------------------------------------------------------------------------
#define RSB   80
#define PARTB 10240
#define STG   20480
#define GSM   (3 * STG)

__global__ __launch_bounds__(128, 2) void hgemm_kernel(
    const fp16* __restrict__ Ah, const fp16* __restrict__ Bh,
    const float* __restrict__ bias, float* __restrict__ C,
    fp16* __restrict__ oqh, fp16* __restrict__ okh, fp16* __restrict__ ovh,
    int M, int N, int K, int mode)
{
    extern __shared__ char smraw[];
    const uint32_t sbase = smem_u32(smraw);
    const int tid = threadIdx.x;
    const int lane = tid & 31;
    const int wid = tid >> 5;
    const int warp_m = wid & 1;      // 2 warps over M (64 rows)
    const int warp_n = wid >> 1;     // 2 warps over N (64 cols)
    const int m0 = blockIdx.y * 128;
    const int n0 = blockIdx.x * 128;

    const fp16* Ah_g = Ah + (size_t)m0 * K;
    const fp16* Bh_g = Bh + (size_t)n0 * K;

    const uint32_t a_lane = (uint32_t)((lane & 15) * RSB + (lane >> 4) * 16
                          + warp_m * 64 * RSB);
    const uint32_t b_lane = (uint32_t)(((lane & 7) + (lane >> 4) * 8) * RSB
                          + ((lane >> 3) & 1) * 16 + warp_n * 64 * RSB);

    float acc[4][8][4];
#pragma unroll
    for (int i = 0; i < 4; i++)
#pragma unroll
        for (int j = 0; j < 8; j++)
#pragma unroll
            for (int q = 0; q < 4; q++) acc[i][j][q] = 0.f;

    const int nch = K >> 5;          // 24

#define LOAD_STAGE(ch) do {                                                    \
        const int k0_ = (ch) << 5;                                             \
        const uint32_t sst = sbase + (uint32_t)((ch) % 3) * STG;               \
        _Pragma("unroll")                                                      \
        for (int s = 0; s < 4; s++) {                                          \
            cp16(sst + tid * RSB + s * 16,                                     \
                 Ah_g + (size_t)tid * K + k0_ + s * 8);                        \
            cp16(sst + PARTB + tid * RSB + s * 16,                             \
                 Bh_g + (size_t)tid * K + k0_ + s * 8);                        \
        }                                                                      \
        CP_COMMIT();                                                           \
    } while (0)

    LOAD_STAGE(0);
    LOAD_STAGE(1);

    for (int ch = 0; ch < nch; ch++) {
        if (ch + 1 < nch) CP_WAIT1(); else CP_WAIT0();
        __syncthreads();
        if (ch + 2 < nch) LOAD_STAGE(ch + 2);

        const uint32_t sbuf = sbase + (uint32_t)(ch % 3) * STG;
        const uint32_t sAh = sbuf + a_lane;
        const uint32_t sBh = sbuf + PARTB + b_lane;

#pragma unroll
        for (int ko = 0; ko < 2; ko++) {
            const uint32_t kb = ko * 32;
            uint32_t bh[4][4];
#pragma unroll
            for (int nt16 = 0; nt16 < 4; nt16++)
                ldsm4(bh[nt16], sBh + nt16 * (16 * RSB) + kb);
#pragma unroll
            for (int mt = 0; mt < 4; mt++) {
                uint32_t ah[4];
                ldsm4(ah, sAh + mt * (16 * RSB) + kb);
#pragma unroll
                for (int nt16 = 0; nt16 < 4; nt16++) {
                    mma_fp16(acc[mt][2 * nt16],     ah, &bh[nt16][0]);
                    mma_fp16(acc[mt][2 * nt16 + 1], ah, &bh[nt16][2]);
                }
            }
        }
    }
#undef LOAD_STAGE

    const int quad = lane >> 2, tq = lane & 3;
    const int region = n0 / 768;
#pragma unroll
    for (int mt = 0; mt < 4; mt++) {
        const int r = m0 + warp_m * 64 + mt * 16 + quad;
#pragma unroll
        for (int nt = 0; nt < 8; nt++) {
            const int c = n0 + warp_n * 64 + nt * 8 + tq * 2;
            const float b0 = bias[c], b1 = bias[c + 1];
            float v0 = acc[mt][nt][0] + b0, v1 = acc[mt][nt][1] + b1;
            float v2 = acc[mt][nt][2] + b0, v3 = acc[mt][nt][3] + b1;
            if (mode == 0) {
                float* cp = C + (size_t)r * N + c;
                *(float2*)cp = make_float2(v0, v1);
                *(float2*)(cp + 8 * (size_t)N) = make_float2(v2, v3);
            } else {
                const int cc = c - region * 768;
                size_t o0 = (size_t)r * 768 + cc;
                size_t o1 = o0 + 8 * 768;
                fp16* dst = (region == 0) ? oqh : (region == 1) ? okh : ovh;
                *(uint32_t*)(dst + o0) = h2pack(v0, v1);
                *(uint32_t*)(dst + o1) = h2pack(v2, v3);
            }
        }
    }
}

// ---------------------------------------------------------------------------
// HMMA flash attention (fp32 acc, pure fp16 operands) — unchanged from R11.
// ---------------------------------------------------------------------------
#define ARS 144
#define A_QH 0
#define A_KH 9216
#define A_VT 18432
#define A_SM 27648

__global__ __launch_bounds__(128) void attn_mma_kernel(
    const fp16* __restrict__ qh, const fp16* __restrict__ kh,
    const fp16* __restrict__ vh,
    const float* __restrict__ biasmat, fp16* __restrict__ out_h)
{
    __shared__ char smem[A_SM];
    const uint32_t sb = smem_u32(smem);
    const int qt = blockIdx.x, h = blockIdx.y, b = blockIdx.z;
    const int tid = threadIdx.x, lane = tid & 31, wid = tid >> 5;
    const int q0 = qt * 64;
    const size_t tok0 = (size_t)b * 256;

    {
        const fp16* qg0 = qh + (tok0 + q0) * 768 + h * 64;
        int row = tid >> 1, sg0 = (tid & 1) * 4;
#pragma unroll
        for (int s = 0; s < 4; s++)
            cp16(sb + A_QH + row * ARS + (sg0 + s) * 16,
                 qg0 + row * 768 + (sg0 + s) * 8);
        CP_COMMIT();
    }

    const uint32_t a_lane = (uint32_t)((lane & 15) * ARS + (lane >> 4) * 16
                          + wid * 16 * ARS);
    const uint32_t b_lane = (uint32_t)(((lane & 7) + (lane >> 4) * 8) * ARS
                          + ((lane >> 3) & 1) * 16);

    float o[8][4];
#pragma unroll
    for (int t = 0; t < 8; t++)
#pragma unroll
        for (int q = 0; q < 4; q++) o[t][q] = 0.f;
    float m0 = -1e30f, m1 = -1e30f, l0 = 0.f, l1 = 0.f;

    const float* bb0 = biasmat + (size_t)h * 65536
                     + (size_t)(q0 + wid * 16 + (lane >> 2)) * 256 + 2 * (lane & 3);

    for (int kt = 0; kt < 4; kt++) {
        __syncthreads();
        {
            const fp16* kg = kh + (tok0 + kt * 64) * 768 + h * 64;
            int row = tid >> 1, sg0 = (tid & 1) * 4;
#pragma unroll
            for (int s = 0; s < 4; s++)
                cp16(sb + A_KH + row * ARS + (sg0 + s) * 16,
                     kg + row * 768 + (sg0 + s) * 8);
            CP_COMMIT();
        }
        {
            const fp16* vg = vh + (tok0 + kt * 64) * 768 + h * 64;
            int key = tid >> 1, dh0 = (tid & 1) * 32;
#pragma unroll
            for (int g = 0; g < 4; g++) {
                float4 vv = *(const float4*)(vg + (size_t)key * 768 + dh0 + g * 8);
                const unsigned short* u = (const unsigned short*)&vv;
#pragma unroll
                for (int e = 0; e < 8; e++)
                    *(unsigned short*)(smem + A_VT + (dh0 + g * 8 + e) * ARS + key * 2) = u[e];
            }
        }
        CP_WAIT0();
        __syncthreads();

        float c[8][4];
#pragma unroll
        for (int t = 0; t < 8; t++)
#pragma unroll
            for (int q = 0; q < 4; q++) c[t][q] = 0.f;

#pragma unroll
        for (int j = 0; j < 4; j++) {
            uint32_t aqh[4];
            ldsm4(aqh, sb + A_QH + a_lane + j * 32);
#pragma unroll
            for (int g = 0; g < 4; g++) {
                uint32_t bk[4];
                ldsm4(bk, sb + A_KH + b_lane + g * (16 * ARS) + j * 32);
                mma_fp16(c[2 * g],     aqh, &bk[0]);
                mma_fp16(c[2 * g + 1], aqh, &bk[2]);
            }
        }

        const float* bk0 = bb0 + kt * 64;
        float tm0 = -1e30f, tm1 = -1e30f;
#pragma unroll
        for (int t = 0; t < 8; t++) {
            float2 bv0 = *(const float2*)(bk0 + t * 8);
            float2 bv1 = *(const float2*)(bk0 + 8 * 256 + t * 8);
            c[t][0] = fmaf(c[t][0], 0.125f, bv0.x);
            c[t][1] = fmaf(c[t][1], 0.125f, bv0.y);
            c[t][2] = fmaf(c[t][2], 0.125f, bv1.x);
            c[t][3] = fmaf(c[t][3], 0.125f, bv1.y);
            tm0 = fmaxf(tm0, fmaxf(c[t][0], c[t][1]));
            tm1 = fmaxf(tm1, fmaxf(c[t][2], c[t][3]));
        }
        tm0 = fmaxf(tm0, __shfl_xor_sync(0xffffffffu, tm0, 1));
        tm0 = fmaxf(tm0, __shfl_xor_sync(0xffffffffu, tm0, 2));
        tm1 = fmaxf(tm1, __shfl_xor_sync(0xffffffffu, tm1, 1));
        tm1 = fmaxf(tm1, __shfl_xor_sync(0xffffffffu, tm1, 2));
        float mn0 = fmaxf(m0, tm0), mn1 = fmaxf(m1, tm1);
        float corr0 = __expf(m0 - mn0), corr1 = __expf(m1 - mn1);
        m0 = mn0; m1 = mn1;
        float ps0 = 0.f, ps1 = 0.f;
#pragma unroll
        for (int t = 0; t < 8; t++) {
            c[t][0] = __expf(c[t][0] - mn0);
            c[t][1] = __expf(c[t][1] - mn0);
            c[t][2] = __expf(c[t][2] - mn1);
            c[t][3] = __expf(c[t][3] - mn1);
            ps0 += c[t][0] + c[t][1];
            ps1 += c[t][2] + c[t][3];
        }
        ps0 += __shfl_xor_sync(0xffffffffu, ps0, 1);
        ps0 += __shfl_xor_sync(0xffffffffu, ps0, 2);
        ps1 += __shfl_xor_sync(0xffffffffu, ps1, 1);
        ps1 += __shfl_xor_sync(0xffffffffu, ps1, 2);
        l0 = l0 * corr0 + ps0;
        l1 = l1 * corr1 + ps1;
#pragma unroll
        for (int t = 0; t < 8; t++) {
            o[t][0] *= corr0; o[t][1] *= corr0;
            o[t][2] *= corr1; o[t][3] *= corr1;
        }

#pragma unroll
        for (int j = 0; j < 4; j++) {
            uint32_t ph[4];
#pragma unroll
            for (int half16 = 0; half16 < 2; half16++) {
                const float* cc = c[2 * j + half16];
                ph[2 * half16]     = h2pack(cc[0], cc[1]);
                ph[2 * half16 + 1] = h2pack(cc[2], cc[3]);
            }
#pragma unroll
            for (int g = 0; g < 4; g++) {
                uint32_t bv[4];
                ldsm4(bv, sb + A_VT + b_lane + g * (16 * ARS) + j * 32);
                mma_fp16(o[2 * g],     ph, &bv[0]);
                mma_fp16(o[2 * g + 1], ph, &bv[2]);
            }
        }
    }

    float inv0 = 1.0f / l0, inv1 = 1.0f / l1;
    const size_t t0 = tok0 + q0 + wid * 16 + (lane >> 2);
    const int colb = h * 64 + 2 * (lane & 3);
#pragma unroll
    for (int t = 0; t < 8; t++) {
        size_t o0 = t0 * 768 + colb + t * 8;
        size_t o1 = o0 + 8 * 768;
        *(uint32_t*)(out_h + o0) = h2pack(o[t][0] * inv0, o[t][1] * inv0);
        *(uint32_t*)(out_h + o1) = h2pack(o[t][2] * inv1, o[t][3] * inv1);
    }
}

// ---------------------------------------------------------------------------
extern "C" void kernel_launch(void* const* d_in, const int* in_sizes, int n_in,
                              void* d_out, int out_size)
{
    const float* x     = (const float*)d_in[0];
    const float* Wqkv  = (const float*)d_in[1];
    const float* bqkv  = (const float*)d_in[2];
    const float* Wout  = (const float*)d_in[3];
    const float* bout  = (const float*)d_in[4];
    const float* table = (const float*)d_in[5];
    const int*   ids   = (const int*)d_in[6];
    float* out = (float*)d_out;

    float* bias;
    fp16 *ah, *qh, *khp, *vhp, *bqh, *boh;
    cudaGetSymbolAddress((void**)&bias, g_bias);
    cudaGetSymbolAddress((void**)&ah,   g_ah);
    cudaGetSymbolAddress((void**)&qh,   g_qh);
    cudaGetSymbolAddress((void**)&khp,  g_kh);
    cudaGetSymbolAddress((void**)&vhp,  g_vh);
    cudaGetSymbolAddress((void**)&bqh,  g_bqh);
    cudaGetSymbolAddress((void**)&boh,  g_boh);

    cudaFuncSetAttribute(hgemm_kernel,
                         cudaFuncAttributeMaxDynamicSharedMemorySize, GSM);

    // prep
    split_transpose_kernel<<<dim3(2304 / 32, 768 / 32), dim3(32, 8)>>>(
        Wqkv, bqh, 768, 2304);
    split_transpose_kernel<<<dim3(768 / 32, 768 / 32), dim3(32, 8)>>>(
        Wout, boh, 768, 768);
    bias_gather_kernel<<<256, 256>>>(ids, table, bias);
    convert_kernel<<<25165824 / 4 / 256, 256>>>(x, ah, 25165824 / 4);

    // QKV projection -> fp16 Q/K/V (hi)
    hgemm_kernel<<<dim3(2304 / 128, 32768 / 128), 128, GSM>>>(
        ah, bqh, bqkv, nullptr, qh, khp, vhp, 32768, 2304, 768, 1);

    // pure-fp16 HMMA attention -> fp16 hi into ah
    attn_mma_kernel<<<dim3(4, 12, 128), 128>>>(qh, khp, vhp, bias, ah);

    // output projection -> fp32 out
    hgemm_kernel<<<dim3(768 / 128, 32768 / 128), 128, GSM>>>(
        ah, boh, bout, out, nullptr, nullptr, nullptr, 32768, 768, 768, 0);
}

// round 16
// speedup vs baseline: 1.0913x; 1.0879x over previous
#include <cuda_runtime.h>
#include <cuda_fp16.h>
#include <cstdint>
#include <cstddef>

// ---------------------------------------------------------------------------
// Attention_87428354277788 — R16: exact R11 math/geometry (pure single-fp16
// HMMA, 8-warp 64x32-warp-tile GEMMs, 16 warps/SM) with BK=32 -> 64:
// 12 pipeline chunks instead of 24 (half the barrier/wait overhead).
// rel_err bit-identical to R11 (6.76e-4).
// ---------------------------------------------------------------------------

typedef unsigned long long u64;
typedef __half fp16;

__device__ float g_bias[786432];       // [12, 256, 256]
__device__ fp16  g_ah[25165824];       // x hi, then attn-out hi [32768,768]
__device__ fp16  g_qh[25165824];       // Q hi [32768,768]
__device__ fp16  g_kh[25165824];       // K hi
__device__ fp16  g_vh[25165824];       // V hi
__device__ fp16  g_bqh[1769472];       // WqkvT hi [2304,768]
__device__ fp16  g_boh[589824];        // WoutT hi [768,768]

// ---------------------------------------------------------------------------
__device__ __forceinline__ uint32_t smem_u32(const void* p) {
    uint32_t a;
    asm("{ .reg .u64 t; cvta.to.shared.u64 t, %1; cvt.u32.u64 %0, t; }"
        : "=r"(a) : "l"(p));
    return a;
}
__device__ __forceinline__ void cp16(uint32_t s, const void* g) {
    asm volatile("cp.async.cg.shared.global [%0], [%1], 16;" :: "r"(s), "l"(g));
}
#define CP_COMMIT() asm volatile("cp.async.commit_group;" ::: "memory")
#define CP_WAIT0()  asm volatile("cp.async.wait_group 0;" ::: "memory")
#define CP_WAIT1()  asm volatile("cp.async.wait_group 1;" ::: "memory")

__device__ __forceinline__ void ldsm4(uint32_t* r, uint32_t addr) {
    asm volatile("ldmatrix.sync.aligned.m8n8.x4.shared.b16 {%0,%1,%2,%3}, [%4];"
        : "=r"(r[0]), "=r"(r[1]), "=r"(r[2]), "=r"(r[3]) : "r"(addr));
}
__device__ __forceinline__ void mma_fp16(float* c, const uint32_t* a,
                                         const uint32_t* b) {
    asm volatile(
        "mma.sync.aligned.m16n8k16.row.col.f32.f16.f16.f32 "
        "{%0,%1,%2,%3}, {%4,%5,%6,%7}, {%8,%9}, {%0,%1,%2,%3};"
        : "+f"(c[0]), "+f"(c[1]), "+f"(c[2]), "+f"(c[3])
        : "r"(a[0]), "r"(a[1]), "r"(a[2]), "r"(a[3]), "r"(b[0]), "r"(b[1]));
}
__device__ __forceinline__ uint32_t h2pack(float a, float b) {
    __half2 h = __floats2half2_rn(a, b);
    return *(uint32_t*)&h;
}

// ---------------------------------------------------------------------------
__global__ void convert_kernel(const float* __restrict__ in,
                               fp16* __restrict__ hi, int n4)
{
    int i = blockIdx.x * 256 + threadIdx.x;
    if (i >= n4) return;
    float4 v = ((const float4*)in)[i];
    ((ushort4*)hi)[i] = make_ushort4(
        __half_as_ushort(__float2half_rn(v.x)),
        __half_as_ushort(__float2half_rn(v.y)),
        __half_as_ushort(__float2half_rn(v.z)),
        __half_as_ushort(__float2half_rn(v.w)));
}

__global__ void split_transpose_kernel(const float* __restrict__ in,
                                       fp16* __restrict__ outh, int R, int C)
{
    __shared__ float t[32][33];
    int c0 = blockIdx.x * 32, r0 = blockIdx.y * 32;
#pragma unroll
    for (int i = threadIdx.y; i < 32; i += 8)
        t[i][threadIdx.x] = in[(size_t)(r0 + i) * C + c0 + threadIdx.x];
    __syncthreads();
#pragma unroll
    for (int i = threadIdx.y; i < 32; i += 8)
        outh[(size_t)(c0 + i) * R + r0 + threadIdx.x] =
            __float2half_rn(t[threadIdx.x][i]);
}

__global__ void bias_gather_kernel(const int* __restrict__ ids,
                                   const float* __restrict__ table,
                                   float* __restrict__ biasmat)
{
    int pos = blockIdx.x * 256 + threadIdx.x;
    int id = ids[pos];
#pragma unroll
    for (int h = 0; h < 12; h++)
        biasmat[h * 65536 + pos] = table[id * 12 + h];
}

// ---------------------------------------------------------------------------
// Single-fp16 GEMM: C = Ah@Bh^T + bias.
// CTA 128x128, 8 warps (2M x 4N, warp tile 64x32), BK=64, 3-stage cp.async,
// 2 CTA/SM (110.6 KB smem/CTA).
// mode 0: fp32 C.  mode 1: QKV epilogue -> Q/K/V hi fp16 [token][768].
// ---------------------------------------------------------------------------
#define RSB   144              // 64 halves (128B) + 16B pad
#define PARTB 18432            // 128 rows * 144
#define STG   36864            // A | B
#define GSM   (3 * STG)        // 110592 B/CTA

__global__ __launch_bounds__(256, 2) void hgemm_kernel(
    const fp16* __restrict__ Ah, const fp16* __restrict__ Bh,
    const float* __restrict__ bias, float* __restrict__ C,
    fp16* __restrict__ oqh, fp16* __restrict__ okh, fp16* __restrict__ ovh,
    int M, int N, int K, int mode)
{
    extern __shared__ char smraw[];
    const uint32_t sbase = smem_u32(smraw);
    const int tid = threadIdx.x;
    const int lane = tid & 31;
    const int wid = tid >> 5;
    const int warp_m = wid & 1;      // 2 warps over M (64 rows)
    const int warp_n = wid >> 1;     // 4 warps over N (32 cols)
    const int m0 = blockIdx.y * 128;
    const int n0 = blockIdx.x * 128;

    const fp16* Ah_g = Ah + (size_t)m0 * K;
    const fp16* Bh_g = Bh + (size_t)n0 * K;

    const uint32_t a_lane = (uint32_t)((lane & 15) * RSB + (lane >> 4) * 16
                          + warp_m * 64 * RSB);
    const uint32_t b_lane = (uint32_t)(((lane & 7) + (lane >> 4) * 8) * RSB
                          + ((lane >> 3) & 1) * 16 + warp_n * 32 * RSB);

    float acc[4][4][4];
#pragma unroll
    for (int i = 0; i < 4; i++)
#pragma unroll
        for (int j = 0; j < 4; j++)
#pragma unroll
            for (int q = 0; q < 4; q++) acc[i][j][q] = 0.f;

    const int nch = K >> 6;          // 12
    const int r_ = tid >> 1;         // 0..127
    const int seg_ = (tid & 1) * 4;  // 0 or 4 (16B units)

#define LOAD_STAGE(ch) do {                                                    \
        const int k0_ = (ch) << 6;                                             \
        const uint32_t sst = sbase + (uint32_t)((ch) % 3) * STG;               \
        _Pragma("unroll")                                                      \
        for (int s = 0; s < 4; s++) {                                          \
            cp16(sst + r_ * RSB + (seg_ + s) * 16,                             \
                 Ah_g + (size_t)r_ * K + k0_ + (seg_ + s) * 8);                \
            cp16(sst + PARTB + r_ * RSB + (seg_ + s) * 16,                     \
                 Bh_g + (size_t)r_ * K + k0_ + (seg_ + s) * 8);                \
        }                                                                      \
        CP_COMMIT();                                                           \
    } while (0)

    LOAD_STAGE(0);
    LOAD_STAGE(1);

    for (int ch = 0; ch < nch; ch++) {
        if (ch + 1 < nch) CP_WAIT1(); else CP_WAIT0();
        __syncthreads();
        if (ch + 2 < nch) LOAD_STAGE(ch + 2);

        const uint32_t sbuf = sbase + (uint32_t)(ch % 3) * STG;
        const uint32_t sAh = sbuf + a_lane;
        const uint32_t sBh = sbuf + PARTB + b_lane;

#pragma unroll
        for (int ko = 0; ko < 4; ko++) {
            const uint32_t kb = ko * 32;       // 16 halves = 32 bytes
            uint32_t bh[2][4];
#pragma unroll
            for (int nt16 = 0; nt16 < 2; nt16++)
                ldsm4(bh[nt16], sBh + nt16 * (16 * RSB) + kb);
#pragma unroll
            for (int mt = 0; mt < 4; mt++) {
                uint32_t ah[4];
                ldsm4(ah, sAh + mt * (16 * RSB) + kb);
#pragma unroll
                for (int nt16 = 0; nt16 < 2; nt16++) {
                    mma_fp16(acc[mt][2 * nt16],     ah, &bh[nt16][0]);
                    mma_fp16(acc[mt][2 * nt16 + 1], ah, &bh[nt16][2]);
                }
            }
        }
    }
#undef LOAD_STAGE

    const int quad = lane >> 2, tq = lane & 3;
    const int region = n0 / 768;
#pragma unroll
    for (int mt = 0; mt < 4; mt++) {
        const int r = m0 + warp_m * 64 + mt * 16 + quad;
#pragma unroll
        for (int nt = 0; nt < 4; nt++) {
            const int c = n0 + warp_n * 32 + nt * 8 + tq * 2;
            const float b0 = bias[c], b1 = bias[c + 1];
            float v0 = acc[mt][nt][0] + b0, v1 = acc[mt][nt][1] + b1;
            float v2 = acc[mt][nt][2] + b0, v3 = acc[mt][nt][3] + b1;
            if (mode == 0) {
                float* cp = C + (size_t)r * N + c;
                *(float2*)cp = make_float2(v0, v1);
                *(float2*)(cp + 8 * (size_t)N) = make_float2(v2, v3);
            } else {
                const int cc = c - region * 768;
                size_t o0 = (size_t)r * 768 + cc;
                size_t o1 = o0 + 8 * 768;
                fp16* dst = (region == 0) ? oqh : (region == 1) ? okh : ovh;
                *(uint32_t*)(dst + o0) = h2pack(v0, v1);
                *(uint32_t*)(dst + o1) = h2pack(v2, v3);
            }
        }
    }
}

// ---------------------------------------------------------------------------
// HMMA flash attention (fp32 acc, pure fp16 operands) — unchanged from R11.
// ---------------------------------------------------------------------------
#define ARS 144
#define A_QH 0
#define A_KH 9216
#define A_VT 18432
#define A_SM 27648

__global__ __launch_bounds__(128) void attn_mma_kernel(
    const fp16* __restrict__ qh, const fp16* __restrict__ kh,
    const fp16* __restrict__ vh,
    const float* __restrict__ biasmat, fp16* __restrict__ out_h)
{
    __shared__ char smem[A_SM];
    const uint32_t sb = smem_u32(smem);
    const int qt = blockIdx.x, h = blockIdx.y, b = blockIdx.z;
    const int tid = threadIdx.x, lane = tid & 31, wid = tid >> 5;
    const int q0 = qt * 64;
    const size_t tok0 = (size_t)b * 256;

    {
        const fp16* qg0 = qh + (tok0 + q0) * 768 + h * 64;
        int row = tid >> 1, sg0 = (tid & 1) * 4;
#pragma unroll
        for (int s = 0; s < 4; s++)
            cp16(sb + A_QH + row * ARS + (sg0 + s) * 16,
                 qg0 + row * 768 + (sg0 + s) * 8);
        CP_COMMIT();
    }

    const uint32_t a_lane = (uint32_t)((lane & 15) * ARS + (lane >> 4) * 16
                          + wid * 16 * ARS);
    const uint32_t b_lane = (uint32_t)(((lane & 7) + (lane >> 4) * 8) * ARS
                          + ((lane >> 3) & 1) * 16);

    float o[8][4];
#pragma unroll
    for (int t = 0; t < 8; t++)
#pragma unroll
        for (int q = 0; q < 4; q++) o[t][q] = 0.f;
    float m0 = -1e30f, m1 = -1e30f, l0 = 0.f, l1 = 0.f;

    const float* bb0 = biasmat + (size_t)h * 65536
                     + (size_t)(q0 + wid * 16 + (lane >> 2)) * 256 + 2 * (lane & 3);

    for (int kt = 0; kt < 4; kt++) {
        __syncthreads();
        {
            const fp16* kg = kh + (tok0 + kt * 64) * 768 + h * 64;
            int row = tid >> 1, sg0 = (tid & 1) * 4;
#pragma unroll
            for (int s = 0; s < 4; s++)
                cp16(sb + A_KH + row * ARS + (sg0 + s) * 16,
                     kg + row * 768 + (sg0 + s) * 8);
            CP_COMMIT();
        }
        {
            const fp16* vg = vh + (tok0 + kt * 64) * 768 + h * 64;
            int key = tid >> 1, dh0 = (tid & 1) * 32;
#pragma unroll
            for (int g = 0; g < 4; g++) {
                float4 vv = *(const float4*)(vg + (size_t)key * 768 + dh0 + g * 8);
                const unsigned short* u = (const unsigned short*)&vv;
#pragma unroll
                for (int e = 0; e < 8; e++)
                    *(unsigned short*)(smem + A_VT + (dh0 + g * 8 + e) * ARS + key * 2) = u[e];
            }
        }
        CP_WAIT0();
        __syncthreads();

        float c[8][4];
#pragma unroll
        for (int t = 0; t < 8; t++)
#pragma unroll
            for (int q = 0; q < 4; q++) c[t][q] = 0.f;

#pragma unroll
        for (int j = 0; j < 4; j++) {
            uint32_t aqh[4];
            ldsm4(aqh, sb + A_QH + a_lane + j * 32);
#pragma unroll
            for (int g = 0; g < 4; g++) {
                uint32_t bk[4];
                ldsm4(bk, sb + A_KH + b_lane + g * (16 * ARS) + j * 32);
                mma_fp16(c[2 * g],     aqh, &bk[0]);
                mma_fp16(c[2 * g + 1], aqh, &bk[2]);
            }
        }

        const float* bk0 = bb0 + kt * 64;
        float tm0 = -1e30f, tm1 = -1e30f;
#pragma unroll
        for (int t = 0; t < 8; t++) {
            float2 bv0 = *(const float2*)(bk0 + t * 8);
            float2 bv1 = *(const float2*)(bk0 + 8 * 256 + t * 8);
            c[t][0] = fmaf(c[t][0], 0.125f, bv0.x);
            c[t][1] = fmaf(c[t][1], 0.125f, bv0.y);
            c[t][2] = fmaf(c[t][2], 0.125f, bv1.x);
            c[t][3] = fmaf(c[t][3], 0.125f, bv1.y);
            tm0 = fmaxf(tm0, fmaxf(c[t][0], c[t][1]));
            tm1 = fmaxf(tm1, fmaxf(c[t][2], c[t][3]));
        }
        tm0 = fmaxf(tm0, __shfl_xor_sync(0xffffffffu, tm0, 1));
        tm0 = fmaxf(tm0, __shfl_xor_sync(0xffffffffu, tm0, 2));
        tm1 = fmaxf(tm1, __shfl_xor_sync(0xffffffffu, tm1, 1));
        tm1 = fmaxf(tm1, __shfl_xor_sync(0xffffffffu, tm1, 2));
        float mn0 = fmaxf(m0, tm0), mn1 = fmaxf(m1, tm1);
        float corr0 = __expf(m0 - mn0), corr1 = __expf(m1 - mn1);
        m0 = mn0; m1 = mn1;
        float ps0 = 0.f, ps1 = 0.f;
#pragma unroll
        for (int t = 0; t < 8; t++) {
            c[t][0] = __expf(c[t][0] - mn0);
            c[t][1] = __expf(c[t][1] - mn0);
            c[t][2] = __expf(c[t][2] - mn1);
            c[t][3] = __expf(c[t][3] - mn1);
            ps0 += c[t][0] + c[t][1];
            ps1 += c[t][2] + c[t][3];
        }
        ps0 += __shfl_xor_sync(0xffffffffu, ps0, 1);
        ps0 += __shfl_xor_sync(0xffffffffu, ps0, 2);
        ps1 += __shfl_xor_sync(0xffffffffu, ps1, 1);
        ps1 += __shfl_xor_sync(0xffffffffu, ps1, 2);
        l0 = l0 * corr0 + ps0;
        l1 = l1 * corr1 + ps1;
#pragma unroll
        for (int t = 0; t < 8; t++) {
            o[t][0] *= corr0; o[t][1] *= corr0;
            o[t][2] *= corr1; o[t][3] *= corr1;
        }

#pragma unroll
        for (int j = 0; j < 4; j++) {
            uint32_t ph[4];
#pragma unroll
            for (int half16 = 0; half16 < 2; half16++) {
                const float* cc = c[2 * j + half16];
                ph[2 * half16]     = h2pack(cc[0], cc[1]);
                ph[2 * half16 + 1] = h2pack(cc[2], cc[3]);
            }
#pragma unroll
            for (int g = 0; g < 4; g++) {
                uint32_t bv[4];
                ldsm4(bv, sb + A_VT + b_lane + g * (16 * ARS) + j * 32);
                mma_fp16(o[2 * g],     ph, &bv[0]);
                mma_fp16(o[2 * g + 1], ph, &bv[2]);
            }
        }
    }

    float inv0 = 1.0f / l0, inv1 = 1.0f / l1;
    const size_t t0 = tok0 + q0 + wid * 16 + (lane >> 2);
    const int colb = h * 64 + 2 * (lane & 3);
#pragma unroll
    for (int t = 0; t < 8; t++) {
        size_t o0 = t0 * 768 + colb + t * 8;
        size_t o1 = o0 + 8 * 768;
        *(uint32_t*)(out_h + o0) = h2pack(o[t][0] * inv0, o[t][1] * inv0);
        *(uint32_t*)(out_h + o1) = h2pack(o[t][2] * inv1, o[t][3] * inv1);
    }
}

// ---------------------------------------------------------------------------
extern "C" void kernel_launch(void* const* d_in, const int* in_sizes, int n_in,
                              void* d_out, int out_size)
{
    const float* x     = (const float*)d_in[0];
    const float* Wqkv  = (const float*)d_in[1];
    const float* bqkv  = (const float*)d_in[2];
    const float* Wout  = (const float*)d_in[3];
    const float* bout  = (const float*)d_in[4];
    const float* table = (const float*)d_in[5];
    const int*   ids   = (const int*)d_in[6];
    float* out = (float*)d_out;

    float* bias;
    fp16 *ah, *qh, *khp, *vhp, *bqh, *boh;
    cudaGetSymbolAddress((void**)&bias, g_bias);
    cudaGetSymbolAddress((void**)&ah,   g_ah);
    cudaGetSymbolAddress((void**)&qh,   g_qh);
    cudaGetSymbolAddress((void**)&khp,  g_kh);
    cudaGetSymbolAddress((void**)&vhp,  g_vh);
    cudaGetSymbolAddress((void**)&bqh,  g_bqh);
    cudaGetSymbolAddress((void**)&boh,  g_boh);

    cudaFuncSetAttribute(hgemm_kernel,
                         cudaFuncAttributeMaxDynamicSharedMemorySize, GSM);

    // prep
    split_transpose_kernel<<<dim3(2304 / 32, 768 / 32), dim3(32, 8)>>>(
        Wqkv, bqh, 768, 2304);
    split_transpose_kernel<<<dim3(768 / 32, 768 / 32), dim3(32, 8)>>>(
        Wout, boh, 768, 768);
    bias_gather_kernel<<<256, 256>>>(ids, table, bias);
    convert_kernel<<<25165824 / 4 / 256, 256>>>(x, ah, 25165824 / 4);

    // QKV projection -> fp16 Q/K/V (hi)
    hgemm_kernel<<<dim3(2304 / 128, 32768 / 128), 256, GSM>>>(
        ah, bqh, bqkv, nullptr, qh, khp, vhp, 32768, 2304, 768, 1);

    // pure-fp16 HMMA attention -> fp16 hi into ah
    attn_mma_kernel<<<dim3(4, 12, 128), 128>>>(qh, khp, vhp, bias, ah);

    // output projection -> fp32 out
    hgemm_kernel<<<dim3(768 / 128, 32768 / 128), 256, GSM>>>(
        ah, boh, bout, out, nullptr, nullptr, nullptr, 32768, 768, 768, 0);
}

// round 17
// speedup vs baseline: 1.3011x; 1.1922x over previous
#include <cuda_runtime.h>
#include <cuda_fp16.h>
#include <cstdint>
#include <cstddef>

// ---------------------------------------------------------------------------
// Attention_87428354277788 — R17: exact R11 (best, 762us) + 4-stage cp.async
// ring (extra latency slack, 80KB/CTA) + exact tail-wait. Math bit-identical
// to R11: pure single-fp16 HMMA GEMMs + HMMA flash attention, rel_err 6.76e-4.
// ---------------------------------------------------------------------------

typedef unsigned long long u64;
typedef __half fp16;

__device__ float g_bias[786432];       // [12, 256, 256]
__device__ fp16  g_ah[25165824];       // x hi, then attn-out hi [32768,768]
__device__ fp16  g_qh[25165824];       // Q hi [32768,768]
__device__ fp16  g_kh[25165824];       // K hi
__device__ fp16  g_vh[25165824];       // V hi
__device__ fp16  g_bqh[1769472];       // WqkvT hi [2304,768]
__device__ fp16  g_boh[589824];        // WoutT hi [768,768]

// ---------------------------------------------------------------------------
__device__ __forceinline__ uint32_t smem_u32(const void* p) {
    uint32_t a;
    asm("{ .reg .u64 t; cvta.to.shared.u64 t, %1; cvt.u32.u64 %0, t; }"
        : "=r"(a) : "l"(p));
    return a;
}
__device__ __forceinline__ void cp16(uint32_t s, const void* g) {
    asm volatile("cp.async.cg.shared.global [%0], [%1], 16;" :: "r"(s), "l"(g));
}
#define CP_COMMIT() asm volatile("cp.async.commit_group;" ::: "memory")
#define CP_WAIT0()  asm volatile("cp.async.wait_group 0;" ::: "memory")
#define CP_WAIT1()  asm volatile("cp.async.wait_group 1;" ::: "memory")
#define CP_WAIT2()  asm volatile("cp.async.wait_group 2;" ::: "memory")

__device__ __forceinline__ void ldsm4(uint32_t* r, uint32_t addr) {
    asm volatile("ldmatrix.sync.aligned.m8n8.x4.shared.b16 {%0,%1,%2,%3}, [%4];"
        : "=r"(r[0]), "=r"(r[1]), "=r"(r[2]), "=r"(r[3]) : "r"(addr));
}
__device__ __forceinline__ void mma_fp16(float* c, const uint32_t* a,
                                         const uint32_t* b) {
    asm volatile(
        "mma.sync.aligned.m16n8k16.row.col.f32.f16.f16.f32 "
        "{%0,%1,%2,%3}, {%4,%5,%6,%7}, {%8,%9}, {%0,%1,%2,%3};"
        : "+f"(c[0]), "+f"(c[1]), "+f"(c[2]), "+f"(c[3])
        : "r"(a[0]), "r"(a[1]), "r"(a[2]), "r"(a[3]), "r"(b[0]), "r"(b[1]));
}
__device__ __forceinline__ uint32_t h2pack(float a, float b) {
    __half2 h = __floats2half2_rn(a, b);
    return *(uint32_t*)&h;
}

// ---------------------------------------------------------------------------
__global__ void convert_kernel(const float* __restrict__ in,
                               fp16* __restrict__ hi, int n4)
{
    int i = blockIdx.x * 256 + threadIdx.x;
    if (i >= n4) return;
    float4 v = ((const float4*)in)[i];
    ((ushort4*)hi)[i] = make_ushort4(
        __half_as_ushort(__float2half_rn(v.x)),
        __half_as_ushort(__float2half_rn(v.y)),
        __half_as_ushort(__float2half_rn(v.z)),
        __half_as_ushort(__float2half_rn(v.w)));
}

__global__ void split_transpose_kernel(const float* __restrict__ in,
                                       fp16* __restrict__ outh, int R, int C)
{
    __shared__ float t[32][33];
    int c0 = blockIdx.x * 32, r0 = blockIdx.y * 32;
#pragma unroll
    for (int i = threadIdx.y; i < 32; i += 8)
        t[i][threadIdx.x] = in[(size_t)(r0 + i) * C + c0 + threadIdx.x];
    __syncthreads();
#pragma unroll
    for (int i = threadIdx.y; i < 32; i += 8)
        outh[(size_t)(c0 + i) * R + r0 + threadIdx.x] =
            __float2half_rn(t[threadIdx.x][i]);
}

__global__ void bias_gather_kernel(const int* __restrict__ ids,
                                   const float* __restrict__ table,
                                   float* __restrict__ biasmat)
{
    int pos = blockIdx.x * 256 + threadIdx.x;
    int id = ids[pos];
#pragma unroll
    for (int h = 0; h < 12; h++)
        biasmat[h * 65536 + pos] = table[id * 12 + h];
}

// ---------------------------------------------------------------------------
// Single-fp16 GEMM: C = Ah@Bh^T + bias.
// CTA 128x128, 8 warps (2M x 4N, warp tile 64x32), BK=32, 4-stage cp.async,
// 2 CTA/SM. mode 0: fp32 C.  mode 1: QKV epilogue -> Q/K/V hi fp16.
// ---------------------------------------------------------------------------
#define RSB   80
#define PARTB 10240
#define STG   20480
#define NSTG  4
#define GSM   (NSTG * STG)     // 81920 B/CTA

__global__ __launch_bounds__(256, 2) void hgemm_kernel(
    const fp16* __restrict__ Ah, const fp16* __restrict__ Bh,
    const float* __restrict__ bias, float* __restrict__ C,
    fp16* __restrict__ oqh, fp16* __restrict__ okh, fp16* __restrict__ ovh,
    int M, int N, int K, int mode)
{
    extern __shared__ char smraw[];
    const uint32_t sbase = smem_u32(smraw);
    const int tid = threadIdx.x;
    const int lane = tid & 31;
    const int wid = tid >> 5;
    const int warp_m = wid & 1;
    const int warp_n = wid >> 1;
    const int m0 = blockIdx.y * 128;
    const int n0 = blockIdx.x * 128;

    const fp16* Ah_g = Ah + (size_t)m0 * K;
    const fp16* Bh_g = Bh + (size_t)n0 * K;

    const uint32_t a_lane = (uint32_t)((lane & 15) * RSB + (lane >> 4) * 16
                          + warp_m * 64 * RSB);
    const uint32_t b_lane = (uint32_t)(((lane & 7) + (lane >> 4) * 8) * RSB
                          + ((lane >> 3) & 1) * 16 + warp_n * 32 * RSB);

    float acc[4][4][4];
#pragma unroll
    for (int i = 0; i < 4; i++)
#pragma unroll
        for (int j = 0; j < 4; j++)
#pragma unroll
            for (int q = 0; q < 4; q++) acc[i][j][q] = 0.f;

    const int nch = K >> 5;          // 24
    const int r_ = tid >> 2, seg_ = tid & 3;

#define LOAD_STAGE(ch) do {                                                    \
        const int k0_ = (ch) << 5;                                             \
        const uint32_t sst = sbase + (uint32_t)((ch) % NSTG) * STG;            \
        _Pragma("unroll")                                                      \
        for (int it = 0; it < 2; it++) {                                       \
            int row = r_ + it * 64;                                            \
            size_t go = (size_t)row * K + k0_ + seg_ * 8;                      \
            uint32_t so = sst + row * RSB + seg_ * 16;                         \
            cp16(so, Ah_g + go);                                               \
            cp16(so + PARTB, Bh_g + go);                                       \
        }                                                                      \
        CP_COMMIT();                                                           \
    } while (0)

    LOAD_STAGE(0);
    LOAD_STAGE(1);
    LOAD_STAGE(2);

    for (int ch = 0; ch < nch; ch++) {
        // wait until chunk ch's group is complete (exact pending count)
        const int rem = nch - 1 - ch;
        if (rem >= 2)      CP_WAIT2();
        else if (rem == 1) CP_WAIT1();
        else               CP_WAIT0();
        __syncthreads();
        if (ch + 3 < nch) LOAD_STAGE(ch + 3);

        const uint32_t sbuf = sbase + (uint32_t)(ch % NSTG) * STG;
        const uint32_t sAh = sbuf + a_lane;
        const uint32_t sBh = sbuf + PARTB + b_lane;

#pragma unroll
        for (int ko = 0; ko < 2; ko++) {
            const uint32_t kb = ko * 32;
            uint32_t bh[2][4];
#pragma unroll
            for (int nt16 = 0; nt16 < 2; nt16++)
                ldsm4(bh[nt16], sBh + nt16 * (16 * RSB) + kb);
#pragma unroll
            for (int mt = 0; mt < 4; mt++) {
                uint32_t ah[4];
                ldsm4(ah, sAh + mt * (16 * RSB) + kb);
#pragma unroll
                for (int nt16 = 0; nt16 < 2; nt16++) {
                    mma_fp16(acc[mt][2 * nt16],     ah, &bh[nt16][0]);
                    mma_fp16(acc[mt][2 * nt16 + 1], ah, &bh[nt16][2]);
                }
            }
        }
    }
#undef LOAD_STAGE

    const int quad = lane >> 2, tq = lane & 3;
    const int region = n0 / 768;
#pragma unroll
    for (int mt = 0; mt < 4; mt++) {
        const int r = m0 + warp_m * 64 + mt * 16 + quad;
#pragma unroll
        for (int nt = 0; nt < 4; nt++) {
            const int c = n0 + warp_n * 32 + nt * 8 + tq * 2;
            const float b0 = bias[c], b1 = bias[c + 1];
            float v0 = acc[mt][nt][0] + b0, v1 = acc[mt][nt][1] + b1;
            float v2 = acc[mt][nt][2] + b0, v3 = acc[mt][nt][3] + b1;
            if (mode == 0) {
                float* cp = C + (size_t)r * N + c;
                *(float2*)cp = make_float2(v0, v1);
                *(float2*)(cp + 8 * (size_t)N) = make_float2(v2, v3);
            } else {
                const int cc = c - region * 768;
                size_t o0 = (size_t)r * 768 + cc;
                size_t o1 = o0 + 8 * 768;
                fp16* dst = (region == 0) ? oqh : (region == 1) ? okh : ovh;
                *(uint32_t*)(dst + o0) = h2pack(v0, v1);
                *(uint32_t*)(dst + o1) = h2pack(v2, v3);
            }
        }
    }
}

// ---------------------------------------------------------------------------
// HMMA flash attention (fp32 acc, pure fp16 operands) — unchanged from R11.
// ---------------------------------------------------------------------------
#define ARS 144
#define A_QH 0
#define A_KH 9216
#define A_VT 18432
#define A_SM 27648

__global__ __launch_bounds__(128) void attn_mma_kernel(
    const fp16* __restrict__ qh, const fp16* __restrict__ kh,
    const fp16* __restrict__ vh,
    const float* __restrict__ biasmat, fp16* __restrict__ out_h)
{
    __shared__ char smem[A_SM];
    const uint32_t sb = smem_u32(smem);
    const int qt = blockIdx.x, h = blockIdx.y, b = blockIdx.z;
    const int tid = threadIdx.x, lane = tid & 31, wid = tid >> 5;
    const int q0 = qt * 64;
    const size_t tok0 = (size_t)b * 256;

    {
        const fp16* qg0 = qh + (tok0 + q0) * 768 + h * 64;
        int row = tid >> 1, sg0 = (tid & 1) * 4;
#pragma unroll
        for (int s = 0; s < 4; s++)
            cp16(sb + A_QH + row * ARS + (sg0 + s) * 16,
                 qg0 + row * 768 + (sg0 + s) * 8);
        CP_COMMIT();
    }

    const uint32_t a_lane = (uint32_t)((lane & 15) * ARS + (lane >> 4) * 16
                          + wid * 16 * ARS);
    const uint32_t b_lane = (uint32_t)(((lane & 7) + (lane >> 4) * 8) * ARS
                          + ((lane >> 3) & 1) * 16);

    float o[8][4];
#pragma unroll
    for (int t = 0; t < 8; t++)
#pragma unroll
        for (int q = 0; q < 4; q++) o[t][q] = 0.f;
    float m0 = -1e30f, m1 = -1e30f, l0 = 0.f, l1 = 0.f;

    const float* bb0 = biasmat + (size_t)h * 65536
                     + (size_t)(q0 + wid * 16 + (lane >> 2)) * 256 + 2 * (lane & 3);

    for (int kt = 0; kt < 4; kt++) {
        __syncthreads();
        {
            const fp16* kg = kh + (tok0 + kt * 64) * 768 + h * 64;
            int row = tid >> 1, sg0 = (tid & 1) * 4;
#pragma unroll
            for (int s = 0; s < 4; s++)
                cp16(sb + A_KH + row * ARS + (sg0 + s) * 16,
                     kg + row * 768 + (sg0 + s) * 8);
            CP_COMMIT();
        }
        {
            const fp16* vg = vh + (tok0 + kt * 64) * 768 + h * 64;
            int key = tid >> 1, dh0 = (tid & 1) * 32;
#pragma unroll
            for (int g = 0; g < 4; g++) {
                float4 vv = *(const float4*)(vg + (size_t)key * 768 + dh0 + g * 8);
                const unsigned short* u = (const unsigned short*)&vv;
#pragma unroll
                for (int e = 0; e < 8; e++)
                    *(unsigned short*)(smem + A_VT + (dh0 + g * 8 + e) * ARS + key * 2) = u[e];
            }
        }
        CP_WAIT0();
        __syncthreads();

        float c[8][4];
#pragma unroll
        for (int t = 0; t < 8; t++)
#pragma unroll
            for (int q = 0; q < 4; q++) c[t][q] = 0.f;

#pragma unroll
        for (int j = 0; j < 4; j++) {
            uint32_t aqh[4];
            ldsm4(aqh, sb + A_QH + a_lane + j * 32);
#pragma unroll
            for (int g = 0; g < 4; g++) {
                uint32_t bk[4];
                ldsm4(bk, sb + A_KH + b_lane + g * (16 * ARS) + j * 32);
                mma_fp16(c[2 * g],     aqh, &bk[0]);
                mma_fp16(c[2 * g + 1], aqh, &bk[2]);
            }
        }

        const float* bk0 = bb0 + kt * 64;
        float tm0 = -1e30f, tm1 = -1e30f;
#pragma unroll
        for (int t = 0; t < 8; t++) {
            float2 bv0 = *(const float2*)(bk0 + t * 8);
            float2 bv1 = *(const float2*)(bk0 + 8 * 256 + t * 8);
            c[t][0] = fmaf(c[t][0], 0.125f, bv0.x);
            c[t][1] = fmaf(c[t][1], 0.125f, bv0.y);
            c[t][2] = fmaf(c[t][2], 0.125f, bv1.x);
            c[t][3] = fmaf(c[t][3], 0.125f, bv1.y);
            tm0 = fmaxf(tm0, fmaxf(c[t][0], c[t][1]));
            tm1 = fmaxf(tm1, fmaxf(c[t][2], c[t][3]));
        }
        tm0 = fmaxf(tm0, __shfl_xor_sync(0xffffffffu, tm0, 1));
        tm0 = fmaxf(tm0, __shfl_xor_sync(0xffffffffu, tm0, 2));
        tm1 = fmaxf(tm1, __shfl_xor_sync(0xffffffffu, tm1, 1));
        tm1 = fmaxf(tm1, __shfl_xor_sync(0xffffffffu, tm1, 2));
        float mn0 = fmaxf(m0, tm0), mn1 = fmaxf(m1, tm1);
        float corr0 = __expf(m0 - mn0), corr1 = __expf(m1 - mn1);
        m0 = mn0; m1 = mn1;
        float ps0 = 0.f, ps1 = 0.f;
#pragma unroll
        for (int t = 0; t < 8; t++) {
            c[t][0] = __expf(c[t][0] - mn0);
            c[t][1] = __expf(c[t][1] - mn0);
            c[t][2] = __expf(c[t][2] - mn1);
            c[t][3] = __expf(c[t][3] - mn1);
            ps0 += c[t][0] + c[t][1];
            ps1 += c[t][2] + c[t][3];
        }
        ps0 += __shfl_xor_sync(0xffffffffu, ps0, 1);
        ps0 += __shfl_xor_sync(0xffffffffu, ps0, 2);
        ps1 += __shfl_xor_sync(0xffffffffu, ps1, 1);
        ps1 += __shfl_xor_sync(0xffffffffu, ps1, 2);
        l0 = l0 * corr0 + ps0;
        l1 = l1 * corr1 + ps1;
#pragma unroll
        for (int t = 0; t < 8; t++) {
            o[t][0] *= corr0; o[t][1] *= corr0;
            o[t][2] *= corr1; o[t][3] *= corr1;
        }

#pragma unroll
        for (int j = 0; j < 4; j++) {
            uint32_t ph[4];
#pragma unroll
            for (int half16 = 0; half16 < 2; half16++) {
                const float* cc = c[2 * j + half16];
                ph[2 * half16]     = h2pack(cc[0], cc[1]);
                ph[2 * half16 + 1] = h2pack(cc[2], cc[3]);
            }
#pragma unroll
            for (int g = 0; g < 4; g++) {
                uint32_t bv[4];
                ldsm4(bv, sb + A_VT + b_lane + g * (16 * ARS) + j * 32);
                mma_fp16(o[2 * g],     ph, &bv[0]);
                mma_fp16(o[2 * g + 1], ph, &bv[2]);
            }
        }
    }

    float inv0 = 1.0f / l0, inv1 = 1.0f / l1;
    const size_t t0 = tok0 + q0 + wid * 16 + (lane >> 2);
    const int colb = h * 64 + 2 * (lane & 3);
#pragma unroll
    for (int t = 0; t < 8; t++) {
        size_t o0 = t0 * 768 + colb + t * 8;
        size_t o1 = o0 + 8 * 768;
        *(uint32_t*)(out_h + o0) = h2pack(o[t][0] * inv0, o[t][1] * inv0);
        *(uint32_t*)(out_h + o1) = h2pack(o[t][2] * inv1, o[t][3] * inv1);
    }
}

// ---------------------------------------------------------------------------
extern "C" void kernel_launch(void* const* d_in, const int* in_sizes, int n_in,
                              void* d_out, int out_size)
{
    const float* x     = (const float*)d_in[0];
    const float* Wqkv  = (const float*)d_in[1];
    const float* bqkv  = (const float*)d_in[2];
    const float* Wout  = (const float*)d_in[3];
    const float* bout  = (const float*)d_in[4];
    const float* table = (const float*)d_in[5];
    const int*   ids   = (const int*)d_in[6];
    float* out = (float*)d_out;

    float* bias;
    fp16 *ah, *qh, *khp, *vhp, *bqh, *boh;
    cudaGetSymbolAddress((void**)&bias, g_bias);
    cudaGetSymbolAddress((void**)&ah,   g_ah);
    cudaGetSymbolAddress((void**)&qh,   g_qh);
    cudaGetSymbolAddress((void**)&khp,  g_kh);
    cudaGetSymbolAddress((void**)&vhp,  g_vh);
    cudaGetSymbolAddress((void**)&bqh,  g_bqh);
    cudaGetSymbolAddress((void**)&boh,  g_boh);

    cudaFuncSetAttribute(hgemm_kernel,
                         cudaFuncAttributeMaxDynamicSharedMemorySize, GSM);

    // prep
    split_transpose_kernel<<<dim3(2304 / 32, 768 / 32), dim3(32, 8)>>>(
        Wqkv, bqh, 768, 2304);
    split_transpose_kernel<<<dim3(768 / 32, 768 / 32), dim3(32, 8)>>>(
        Wout, boh, 768, 768);
    bias_gather_kernel<<<256, 256>>>(ids, table, bias);
    convert_kernel<<<25165824 / 4 / 256, 256>>>(x, ah, 25165824 / 4);

    // QKV projection -> fp16 Q/K/V (hi)
    hgemm_kernel<<<dim3(2304 / 128, 32768 / 128), 256, GSM>>>(
        ah, bqh, bqkv, nullptr, qh, khp, vhp, 32768, 2304, 768, 1);

    // pure-fp16 HMMA attention -> fp16 hi into ah
    attn_mma_kernel<<<dim3(4, 12, 128), 128>>>(qh, khp, vhp, bias, ah);

    // output projection -> fp32 out
    hgemm_kernel<<<dim3(768 / 128, 32768 / 128), 256, GSM>>>(
        ah, boh, bout, out, nullptr, nullptr, nullptr, 32768, 768, 768, 0);
}